// round 3
// baseline (speedup 1.0000x reference)
#include <cuda_runtime.h>
#include <math_constants.h>

// ---------------------------------------------------------------------------
// MAB: ragged multi-head attention block.
//   qp = q@Wq+bq ; kp = k@Wk+bk ; vp = k@Wv+bv   (kp/vp fused: shared A operand)
//   per (batch,head): flash attention over the batch's tokens, + qp residual
//   out = ao + relu(ao@Wo + bo)
// ---------------------------------------------------------------------------

#define NMAX 16384
#define BBATCH 16

__device__ float g_qp[NMAX * 256];
__device__ float g_kp[NMAX * 256];
__device__ float g_vp[NMAX * 256];
__device__ float g_ao[NMAX * 256];
__device__ int   g_starts[BBATCH + 1];

// --------------------------- batch start offsets ---------------------------
__global__ void starts_kernel(const int* __restrict__ batch, int N) {
    int b = threadIdx.x;
    if (b > BBATCH) return;
    int lo = 0, hi = N;
    while (lo < hi) {
        int mid = (lo + hi) >> 1;
        if (batch[mid] < b) lo = mid + 1; else hi = mid;
    }
    g_starts[b] = lo;
}

// ------------------------------- SGEMM --------------------------------------
// MODE 0: C  = A@W  + bias
// MODE 1: C  = R + relu(A@W + bias)
// MODE 2: C  = A@W + bias  AND  C2 = A@W2 + bias2   (fused dual GEMM, shared A)
template <int MODE>
__global__ void __launch_bounds__(256)
gemm_kernel(const float* __restrict__ A, const float* __restrict__ W,
            const float* __restrict__ bias, const float* __restrict__ R,
            float* __restrict__ C,
            const float* __restrict__ W2, const float* __restrict__ bias2,
            float* __restrict__ C2, int N) {
    const int BM = 128, BN = 64, BK = 16;
    __shared__ float As[BK][BM];   // transposed A tile
    __shared__ float Ws[BK][BN];
    __shared__ float Ws2[(MODE == 2) ? BK : 1][(MODE == 2) ? BN : 1];

    int tid = threadIdx.x;
    int bm0 = blockIdx.x * BM;
    int bn0 = blockIdx.y * BN;
    int tx = tid & 15;             // 16 column groups of 4
    int ty = tid >> 4;             // 16 row groups of 8

    float acc[8][4];
    float acc2[(MODE == 2) ? 8 : 1][(MODE == 2) ? 4 : 1];
#pragma unroll
    for (int i = 0; i < 8; i++)
#pragma unroll
        for (int j = 0; j < 4; j++) acc[i][j] = 0.f;
    if (MODE == 2) {
#pragma unroll
        for (int i = 0; i < 8; i++)
#pragma unroll
            for (int j = 0; j < 4; j++) acc2[i][j] = 0.f;
    }

    for (int k0 = 0; k0 < 256; k0 += BK) {
        // load A tile (128 rows x 16 k), store transposed
#pragma unroll
        for (int i = 0; i < 2; i++) {
            int f = tid + i * 256;          // 0..511 float4 slots
            int row = f >> 2;               // 0..127
            int kq = f & 3;                 // float4 within the 16-wide k slice
            float4 v = make_float4(0.f, 0.f, 0.f, 0.f);
            int grow = bm0 + row;
            if (grow < N)
                v = *(const float4*)(A + (size_t)grow * 256 + k0 + kq * 4);
            As[kq * 4 + 0][row] = v.x;
            As[kq * 4 + 1][row] = v.y;
            As[kq * 4 + 2][row] = v.z;
            As[kq * 4 + 3][row] = v.w;
        }
        // load W tile(s) (16 k rows x 64 cols)
        {
            int kk = tid >> 4;
            int cq = tid & 15;
            float4 v = *(const float4*)(W + (size_t)(k0 + kk) * 256 + bn0 + cq * 4);
            *(float4*)&Ws[kk][cq * 4] = v;
            if (MODE == 2) {
                float4 v2 = *(const float4*)(W2 + (size_t)(k0 + kk) * 256 + bn0 + cq * 4);
                *(float4*)&Ws2[kk][cq * 4] = v2;
            }
        }
        __syncthreads();

#pragma unroll
        for (int kk = 0; kk < BK; kk++) {
            float4 w  = *(const float4*)&Ws[kk][tx * 4];
            float4 a0 = *(const float4*)&As[kk][ty * 8];
            float4 a1 = *(const float4*)&As[kk][ty * 8 + 4];
            float av[8] = {a0.x, a0.y, a0.z, a0.w, a1.x, a1.y, a1.z, a1.w};
#pragma unroll
            for (int i = 0; i < 8; i++) {
                acc[i][0] += av[i] * w.x;
                acc[i][1] += av[i] * w.y;
                acc[i][2] += av[i] * w.z;
                acc[i][3] += av[i] * w.w;
            }
            if (MODE == 2) {
                float4 w2 = *(const float4*)&Ws2[kk][tx * 4];
#pragma unroll
                for (int i = 0; i < 8; i++) {
                    acc2[i][0] += av[i] * w2.x;
                    acc2[i][1] += av[i] * w2.y;
                    acc2[i][2] += av[i] * w2.z;
                    acc2[i][3] += av[i] * w2.w;
                }
            }
        }
        __syncthreads();
    }

    float4 bv4 = *(const float4*)(bias + bn0 + tx * 4);
    float4 bv4b = (MODE == 2) ? *(const float4*)(bias2 + bn0 + tx * 4)
                              : make_float4(0.f, 0.f, 0.f, 0.f);
#pragma unroll
    for (int i = 0; i < 8; i++) {
        int row = bm0 + ty * 8 + i;
        if (row < N) {
            float4 o;
            o.x = acc[i][0] + bv4.x;
            o.y = acc[i][1] + bv4.y;
            o.z = acc[i][2] + bv4.z;
            o.w = acc[i][3] + bv4.w;
            if (MODE == 1) {
                float4 r = *(const float4*)(R + (size_t)row * 256 + bn0 + tx * 4);
                o.x = r.x + fmaxf(o.x, 0.f);
                o.y = r.y + fmaxf(o.y, 0.f);
                o.z = r.z + fmaxf(o.z, 0.f);
                o.w = r.w + fmaxf(o.w, 0.f);
            }
            *(float4*)(C + (size_t)row * 256 + bn0 + tx * 4) = o;
            if (MODE == 2) {
                float4 o2;
                o2.x = acc2[i][0] + bv4b.x;
                o2.y = acc2[i][1] + bv4b.y;
                o2.z = acc2[i][2] + bv4b.z;
                o2.w = acc2[i][3] + bv4b.w;
                *(float4*)(C2 + (size_t)row * 256 + bn0 + tx * 4) = o2;
            }
        }
    }
}

// ---------------------------- flash attention -------------------------------
// grid: (qtiles, H, B); block: 128 threads, one query per thread.
// K/V streamed in 32-key SMEM tiles; online softmax in 16-key chunks so the
// score buffer stays statically indexed (registers, no LMEM).
__global__ void __launch_bounds__(128)
attn_kernel(const float* __restrict__ qp, const float* __restrict__ kp,
            const float* __restrict__ vp, float* __restrict__ ao) {
    const int KT = 32;
    __shared__ float Ks[KT][32];
    __shared__ float Vs[KT][32];

    int b = blockIdx.z;
    int h = blockIdx.y;
    int s0 = g_starts[b];
    int L  = g_starts[b + 1] - s0;
    if ((int)(blockIdx.x * 128) >= L) return;

    int qi = blockIdx.x * 128 + threadIdx.x;
    bool active = (qi < L);
    int qrow = s0 + (active ? qi : 0);

    float Q[32];
    {
        const float* qr = qp + (size_t)qrow * 256 + (h << 5);
#pragma unroll
        for (int dq = 0; dq < 8; dq++) {
            float4 v = ((const float4*)qr)[dq];
            Q[dq * 4 + 0] = v.x;
            Q[dq * 4 + 1] = v.y;
            Q[dq * 4 + 2] = v.z;
            Q[dq * 4 + 3] = v.w;
        }
    }

    const float scale = 0.17677669529663687f;  // 1/sqrt(32)
    float m = -1e30f, l = 0.f;
    float O[32];
#pragma unroll
    for (int d = 0; d < 32; d++) O[d] = 0.f;

    int nt = (L + KT - 1) / KT;
    for (int kt = 0; kt < nt; kt++) {
        int kbase = kt * KT;
        // cooperative K/V tile load: 256 float4 per tensor, 2 per thread
#pragma unroll
        for (int i = 0; i < 2; i++) {
            int f = threadIdx.x + i * 128;   // 0..255
            int j = f >> 3;
            int dq = f & 7;
            int kr = kbase + j;
            float4 kv = make_float4(0.f, 0.f, 0.f, 0.f);
            float4 vv = kv;
            if (kr < L) {
                const float* kpr = kp + (size_t)(s0 + kr) * 256 + (h << 5);
                const float* vpr = vp + (size_t)(s0 + kr) * 256 + (h << 5);
                kv = ((const float4*)kpr)[dq];
                vv = ((const float4*)vpr)[dq];
            }
            *(float4*)&Ks[j][dq * 4] = kv;
            *(float4*)&Vs[j][dq * 4] = vv;
        }
        __syncthreads();

#pragma unroll 1
        for (int c = 0; c < 2; c++) {
            int cb = kbase + c * 16;
            float s[16];
            float tmax = -1e30f;
#pragma unroll
            for (int j = 0; j < 16; j++) {
                float acc = 0.f;
#pragma unroll
                for (int dq = 0; dq < 8; dq++) {
                    float4 k4 = *(const float4*)&Ks[c * 16 + j][dq * 4];
                    acc += Q[dq * 4 + 0] * k4.x;
                    acc += Q[dq * 4 + 1] * k4.y;
                    acc += Q[dq * 4 + 2] * k4.z;
                    acc += Q[dq * 4 + 3] * k4.w;
                }
                s[j] = (cb + j < L) ? acc * scale : -1e30f;
                tmax = fmaxf(tmax, s[j]);
            }
            float mnew = fmaxf(m, tmax);
            float corr = __expf(m - mnew);
            l *= corr;
#pragma unroll
            for (int d = 0; d < 32; d++) O[d] *= corr;
#pragma unroll
            for (int j = 0; j < 16; j++) {
                float p = __expf(s[j] - mnew);
                l += p;
#pragma unroll
                for (int dq = 0; dq < 8; dq++) {
                    float4 v4 = *(const float4*)&Vs[c * 16 + j][dq * 4];
                    O[dq * 4 + 0] += p * v4.x;
                    O[dq * 4 + 1] += p * v4.y;
                    O[dq * 4 + 2] += p * v4.z;
                    O[dq * 4 + 3] += p * v4.w;
                }
            }
            m = mnew;
        }
        __syncthreads();
    }

    if (active) {
        float inv = 1.f / l;
        const float* qr = qp + (size_t)(s0 + qi) * 256 + (h << 5);
        float* orow = ao + (size_t)(s0 + qi) * 256 + (h << 5);
#pragma unroll
        for (int dq = 0; dq < 8; dq++) {
            float4 qv = ((const float4*)qr)[dq];
            float4 ov;
            ov.x = O[dq * 4 + 0] * inv + qv.x;
            ov.y = O[dq * 4 + 1] * inv + qv.y;
            ov.z = O[dq * 4 + 2] * inv + qv.z;
            ov.w = O[dq * 4 + 3] * inv + qv.w;
            ((float4*)orow)[dq] = ov;
        }
    }
}

// ------------------------------ launcher ------------------------------------
extern "C" void kernel_launch(void* const* d_in, const int* in_sizes, int n_in,
                              void* d_out, int out_size) {
    const float* q       = (const float*)d_in[0];
    const float* k       = (const float*)d_in[1];
    const int*   batch_q = (const int*)d_in[2];
    // d_in[3] = batch_k (identical to batch_q)
    const float* Wq = (const float*)d_in[4];
    const float* bq = (const float*)d_in[5];
    const float* Wk = (const float*)d_in[6];
    const float* bk = (const float*)d_in[7];
    const float* Wv = (const float*)d_in[8];
    const float* bv = (const float*)d_in[9];
    const float* Wo = (const float*)d_in[10];
    const float* bo = (const float*)d_in[11];
    float* out = (float*)d_out;

    int N = in_sizes[0] / 256;

    void *p_qp, *p_kp, *p_vp, *p_ao;
    cudaGetSymbolAddress(&p_qp, g_qp);
    cudaGetSymbolAddress(&p_kp, g_kp);
    cudaGetSymbolAddress(&p_vp, g_vp);
    cudaGetSymbolAddress(&p_ao, g_ao);
    float* qp = (float*)p_qp;
    float* kp = (float*)p_kp;
    float* vp = (float*)p_vp;
    float* ao = (float*)p_ao;

    starts_kernel<<<1, 32>>>(batch_q, N);

    dim3 gg((N + 127) / 128, 4);
    // qp = q@Wq + bq
    gemm_kernel<0><<<gg, 256>>>(q, Wq, bq, nullptr, qp,
                                nullptr, nullptr, nullptr, N);
    // kp = k@Wk + bk ; vp = k@Wv + bv  (fused: k's A-tiles loaded once)
    gemm_kernel<2><<<gg, 256>>>(k, Wk, bk, nullptr, kp,
                                Wv, bv, vp, N);

    dim3 ga(8 /* ceil(1024/128) */, 8 /* H */, BBATCH);
    attn_kernel<<<ga, 128>>>(qp, kp, vp, ao);

    // out = ao + relu(ao@Wo + bo)
    gemm_kernel<1><<<gg, 256>>>(ao, Wo, bo, ao, out,
                                nullptr, nullptr, nullptr, N);
}